// round 11
// baseline (speedup 1.0000x reference)
#include <cuda_runtime.h>
#include <math.h>
#include <stdint.h>

#define BDIM 8192
#define DDIM 512
#define INV_T (1.0f/0.07f)
#define LSE_C (1.0f/0.07f)

#define BM 128
#define KC 128                        // s8 elements per stage (128 B per row)
#define NKC (DDIM/KC)                 // 4
#define NTILE (BDIM/BM)               // 64
#define TOT_TILES (NTILE*(NTILE+1)/2) // 2080
#define PLCAP 256
#define NSTAGE 3

#define TILE_B (BM*KC)                // 16384 B per s8 tile (128 B/row)
#define STAGE_B (2*TILE_B)            // A + B = 32 KB
#define SMEM_BYTES (NSTAGE*STAGE_B + 2048)

// ---- device scratch ----
__device__ int8_t g_Eq[BDIM*DDIM];
__device__ float  g_rscale[BDIM];
__device__ float  g_rowsum[BDIM];
__device__ float  g_pl[BDIM*PLCAP];
__device__ int    g_plcnt[BDIM];
__device__ double g_acc;

// ---------------------------------------------------------------------------
// fp32 -> per-row-scaled int8, fused with init. One warp per row.
__global__ void convert_kernel(const float* __restrict__ E) {
    const int warp = (blockIdx.x * blockDim.x + threadIdx.x) >> 5;  // row
    const int lane = threadIdx.x & 31;
    if (warp >= BDIM) return;

    const float4* src = reinterpret_cast<const float4*>(E + (size_t)warp * DDIM) + lane * 4;
    float4 v[4];
    float mx = 0.f;
#pragma unroll
    for (int i = 0; i < 4; i++) {
        v[i] = src[i];
        mx = fmaxf(mx, fmaxf(fmaxf(fabsf(v[i].x), fabsf(v[i].y)),
                             fmaxf(fabsf(v[i].z), fabsf(v[i].w))));
    }
#pragma unroll
    for (int o = 16; o > 0; o >>= 1) mx = fmaxf(mx, __shfl_xor_sync(0xffffffffu, mx, o));

    const float inv = 127.f / mx;
    uint32_t p[4];
#pragma unroll
    for (int i = 0; i < 4; i++) {
        int q0 = __float2int_rn(v[i].x * inv);
        int q1 = __float2int_rn(v[i].y * inv);
        int q2 = __float2int_rn(v[i].z * inv);
        int q3 = __float2int_rn(v[i].w * inv);
        p[i] = (uint32_t)(q0 & 0xff) | ((uint32_t)(q1 & 0xff) << 8)
             | ((uint32_t)(q2 & 0xff) << 16) | ((uint32_t)(q3 & 0xff) << 24);
    }
    reinterpret_cast<uint4*>(g_Eq + (size_t)warp * DDIM)[lane] =
        make_uint4(p[0], p[1], p[2], p[3]);

    if (lane == 0) {
        g_rscale[warp] = mx * (1.f / 127.f);
        g_plcnt[warp] = 0;
        g_rowsum[warp] = 0.f;
        if (warp == 0) g_acc = 0.0;
    }
}

// ---------------------------------------------------------------------------
__device__ __forceinline__ void cp16(uint32_t dst, const void* src) {
    asm volatile("cp.async.cg.shared.global [%0], [%1], 16;\n" :: "r"(dst), "l"(src));
}
#define CP_COMMIT() asm volatile("cp.async.commit_group;\n" ::: "memory")
#define CP_WAIT(n)  asm volatile("cp.async.wait_group %0;\n" :: "n"(n) : "memory")

__device__ __forceinline__ void ldsm4(uint32_t& r0, uint32_t& r1, uint32_t& r2, uint32_t& r3,
                                      uint32_t addr) {
    asm volatile("ldmatrix.sync.aligned.m8n8.x4.shared.b16 {%0,%1,%2,%3}, [%4];"
                 : "=r"(r0), "=r"(r1), "=r"(r2), "=r"(r3) : "r"(addr));
}

__device__ __forceinline__ void mma_s8(int c[4], const uint32_t a[4], uint32_t b0, uint32_t b1) {
    asm volatile(
        "mma.sync.aligned.m16n8k32.row.col.s32.s8.s8.s32 "
        "{%0,%1,%2,%3}, {%4,%5,%6,%7}, {%8,%9}, {%0,%1,%2,%3};"
        : "+r"(c[0]), "+r"(c[1]), "+r"(c[2]), "+r"(c[3])
        : "r"(a[0]), "r"(a[1]), "r"(a[2]), "r"(a[3]), "r"(b0), "r"(b1));
}

// ---------------------------------------------------------------------------
// Symmetric-tile fused int8 GEMM+LSE. One upper-triangle 128x128 tile per CTA.
// grid TOT_TILES, block 256 (8 warps: 2M x 4N), warp tile 64x32.
// 3-stage cp.async ring, KC=128 s8 elems, 4 k-chunks.
extern __shared__ __align__(16) char dynsmem[];

__global__ void __launch_bounds__(256, 2)
lse_gemm_kernel(const int* __restrict__ lab) {
    int*   labA = (int*)(dynsmem + NSTAGE * STAGE_B);
    int*   labB = labA + 128;
    float* sclA = (float*)(labB + 128);
    float* sclB = sclA + 128;
    const uint32_t smem_base = (uint32_t)__cvta_generic_to_shared(dynsmem);

    // decode upper-triangle tile (I, J), J >= I
    int I = 0, rem = blockIdx.x;
    while (rem >= (NTILE - I)) { rem -= (NTILE - I); I++; }
    const int J = I + rem;
    const int row0 = I * BM;
    const int col0 = J * BM;
    const bool offdiag = (I != J);

    const int tid    = threadIdx.x;
    const int lane   = tid & 31;
    const int warpid = tid >> 5;
    const int warpM0 = (warpid >> 2) * 64;
    const int warpN0 = (warpid & 3) * 32;

    // ldmatrix per-lane geometry; s8-k32 fragments are byte-identical to f16-k16
    const int li = lane & 7, lm = lane >> 3;
    const int rA    = warpM0 + li + (lm & 1) * 8;
    const int kAoff = lm >> 1;
    const int nB    = warpN0 + li + (lm >> 1) * 8;
    const int kBoff = lm & 1;
    const int sA    = li;
    const int sB    = li;

    if (tid < 128) { labA[tid] = lab[row0 + tid]; sclA[tid] = g_rscale[row0 + tid]; }
    else { labB[tid-128] = lab[col0 + tid-128]; sclB[tid-128] = g_rscale[col0 + tid-128]; }

    int acc[4][4][4];
#pragma unroll
    for (int mt = 0; mt < 4; mt++)
#pragma unroll
        for (int nt = 0; nt < 4; nt++)
#pragma unroll
            for (int e = 0; e < 4; e++) acc[mt][nt][e] = 0;

    auto load_stage = [&](int stage, int kc) {
        const int ke = kc * KC;
        const uint32_t sbase = smem_base + stage * STAGE_B;
#pragma unroll
        for (int half = 0; half < 4; half++) {
            const int c = tid + half * 256;          // 0..1023
            const int row = c >> 3, chk = c & 7;
            const uint32_t doff = (uint32_t)(row * 8 + (chk ^ (row & 7))) * 16;
            const size_t aoff = (size_t)(row0 + row) * DDIM + ke + chk * 16;
            const size_t boff = (size_t)(col0 + row) * DDIM + ke + chk * 16;
            cp16(sbase + 0 * TILE_B + doff, g_Eq + aoff);
            cp16(sbase + 1 * TILE_B + doff, g_Eq + boff);
        }
        CP_COMMIT();
    };

    load_stage(0, 0);
    load_stage(1, 1);

    int stage = 0;
    for (int kc = 0; kc < NKC; kc++) {
        if (kc + 1 < NKC) { CP_WAIT(1); } else { CP_WAIT(0); }
        __syncthreads();

        if (kc + 2 < NKC) {
            int ns = stage + 2; if (ns >= NSTAGE) ns -= NSTAGE;
            load_stage(ns, kc + 2);
        }

        const uint32_t sbase = smem_base + stage * STAGE_B;
#pragma unroll
        for (int kk = 0; kk < 4; kk++) {           // each kk = k32 s8
            uint32_t a[4][4], b[2][4];
#pragma unroll
            for (int mt = 0; mt < 4; mt++) {
                uint32_t addr = sbase + 0 * TILE_B +
                    (uint32_t)((rA + mt * 16) * 8 + ((kk * 2 + kAoff) ^ sA)) * 16;
                ldsm4(a[mt][0], a[mt][1], a[mt][2], a[mt][3], addr);
            }
#pragma unroll
            for (int np = 0; np < 2; np++) {
                uint32_t addr = sbase + 1 * TILE_B +
                    (uint32_t)((nB + np * 16) * 8 + ((kk * 2 + kBoff) ^ sB)) * 16;
                ldsm4(b[np][0], b[np][1], b[np][2], b[np][3], addr);
            }
#pragma unroll
            for (int mt = 0; mt < 4; mt++)
#pragma unroll
                for (int np = 0; np < 2; np++) {
                    mma_s8(acc[mt][2 * np + 0], a[mt], b[np][0], b[np][1]);
                    mma_s8(acc[mt][2 * np + 1], a[mt], b[np][2], b[np][3]);
                }
        }
        if (++stage >= NSTAGE) stage -= NSTAGE;
    }
    __syncthreads();

    // ---- epilogue: dequant + row sums + (off-diag) col sums + scatter ----
    int rlab[8], clab[8];
    float rscl[8], cscl[8];
#pragma unroll
    for (int mt = 0; mt < 4; mt++)
#pragma unroll
        for (int h = 0; h < 2; h++) {
            const int rr = warpM0 + mt * 16 + (lane >> 2) + h * 8;
            rlab[mt * 2 + h] = labA[rr];
            rscl[mt * 2 + h] = sclA[rr] * INV_T;
        }
#pragma unroll
    for (int nt = 0; nt < 4; nt++)
#pragma unroll
        for (int j = 0; j < 2; j++) {
            const int cc = warpN0 + nt * 8 + (lane & 3) * 2 + j;
            clab[nt * 2 + j] = labB[cc];
            cscl[nt * 2 + j] = sclB[cc];
        }

    float colAcc[8];
#pragma unroll
    for (int i = 0; i < 8; i++) colAcc[i] = 0.f;

#pragma unroll
    for (int mt = 0; mt < 4; mt++)
#pragma unroll
        for (int h = 0; h < 2; h++) {
            const int gr = row0 + warpM0 + mt * 16 + (lane >> 2) + h * 8;
            const float rs = rscl[mt * 2 + h];
            float s = 0.f;
#pragma unroll
            for (int nt = 0; nt < 4; nt++)
#pragma unroll
                for (int j = 0; j < 2; j++) {
                    const float v = __int2float_rn(acc[mt][nt][h * 2 + j]) * rs * cscl[nt * 2 + j];
                    const int gc = col0 + warpN0 + nt * 8 + (lane & 3) * 2 + j;
                    if (clab[nt * 2 + j] == rlab[mt * 2 + h]) {
                        if (gc != gr) {
                            int idx = atomicAdd(&g_plcnt[gr], 1);
                            if (idx < PLCAP) g_pl[gr * PLCAP + idx] = v;
                            if (offdiag) {
                                int idc = atomicAdd(&g_plcnt[gc], 1);
                                if (idc < PLCAP) g_pl[gc * PLCAP + idc] = v;
                            }
                        }
                    } else {
                        const float e = __expf(v - LSE_C);
                        s += e;
                        colAcc[nt * 2 + j] += e;
                    }
                }
            s += __shfl_xor_sync(0xffffffffu, s, 1);
            s += __shfl_xor_sync(0xffffffffu, s, 2);
            if ((lane & 3) == 0) atomicAdd(&g_rowsum[gr], s);
        }

    if (offdiag) {
#pragma unroll
        for (int idx = 0; idx < 8; idx++) {
            float cs = colAcc[idx];
            cs += __shfl_xor_sync(0xffffffffu, cs, 4);
            cs += __shfl_xor_sync(0xffffffffu, cs, 8);
            cs += __shfl_xor_sync(0xffffffffu, cs, 16);
            if ((lane >> 2) == 0) {
                const int gc = col0 + warpN0 + (idx >> 1) * 8 + (lane & 3) * 2 + (idx & 1);
                atomicAdd(&g_rowsum[gc], cs);
            }
        }
    }
}

// ---------------------------------------------------------------------------
// One warp per row: base = LSE_C + log(rowsum); sum softplus(base - l).
__global__ void pair_kernel() {
    const int warp = (blockIdx.x * blockDim.x + threadIdx.x) >> 5;
    const int lane = threadIdx.x & 31;
    if (warp >= BDIM) return;
    int cnt = g_plcnt[warp];
    if (cnt > PLCAP) cnt = PLCAP;
    const float base = LSE_C + logf(g_rowsum[warp]);
    float rowsum = 0.f;
    for (int t = lane; t < cnt; t += 32) {
        const float l = g_pl[warp * PLCAP + t];
        const float x = base - l;
        rowsum += (x > 0.f) ? x + log1pf(expf(-x)) : log1pf(expf(x));
    }
#pragma unroll
    for (int o = 16; o > 0; o >>= 1) rowsum += __shfl_xor_sync(0xffffffffu, rowsum, o);
    if (lane == 0 && cnt > 0)
        atomicAdd(&g_acc, (double)(rowsum / (float)cnt));
}

__global__ void finalize_kernel(float* out) {
    out[0] = (float)(g_acc / (double)BDIM);
}

// ---------------------------------------------------------------------------
extern "C" void kernel_launch(void* const* d_in, const int* in_sizes, int n_in,
                              void* d_out, int out_size) {
    const float* E   = nullptr;
    const int*   lab = nullptr;
    for (int i = 0; i < n_in; i++) {
        if (in_sizes[i] == BDIM * DDIM) E   = (const float*)d_in[i];
        else if (in_sizes[i] == BDIM)   lab = (const int*)d_in[i];
    }
    float* out = (float*)d_out;

    cudaFuncSetAttribute(lse_gemm_kernel,
                         cudaFuncAttributeMaxDynamicSharedMemorySize, SMEM_BYTES);

    convert_kernel<<<BDIM / 8, 256>>>(E);            // 8 warps per block, fused init
    lse_gemm_kernel<<<TOT_TILES, 256, SMEM_BYTES>>>(lab);
    pair_kernel<<<BDIM / 8, 256>>>();
    finalize_kernel<<<1, 1>>>(out);
}

// round 12
// speedup vs baseline: 1.3658x; 1.3658x over previous
#include <cuda_runtime.h>
#include <cuda_fp16.h>
#include <math.h>
#include <stdint.h>

#define BDIM 8192
#define DDIM 512
#define INV_T (1.0f/0.07f)
#define LSE_C (1.0f/0.07f)

#define BM 128
#define KC 64
#define NKC (DDIM/KC)                 // 8
#define NTILE (BDIM/BM)               // 64
#define TOT_TILES (NTILE*(NTILE+1)/2) // 2080
#define PLCAP 256
#define NSTAGE 3

#define TILE_B (BM*KC*2)              // 16384 B per fp16 tile (128 B/row)
#define STAGE_B (2*TILE_B)            // A + B = 32 KB
#define SMEM_BYTES (NSTAGE*STAGE_B + 1024)

// ---- device scratch ----
__device__ __half g_Eh[BDIM*DDIM];
__device__ float  g_rowsum[BDIM];
__device__ float  g_pl[BDIM*PLCAP];
__device__ int    g_plcnt[BDIM];
__device__ double g_acc;
__device__ int    g_ticket;

// ---------------------------------------------------------------------------
// fp32 -> fp16, fused with state init.
__global__ void convert_kernel(const float* __restrict__ E) {
    int i = blockIdx.x * blockDim.x + threadIdx.x;   // over BDIM*DDIM/4
    float4 v = reinterpret_cast<const float4*>(E)[i];
    __half2* dst = reinterpret_cast<__half2*>(g_Eh) + 2 * i;
    dst[0] = __floats2half2_rn(v.x, v.y);
    dst[1] = __floats2half2_rn(v.z, v.w);
    if (i < BDIM) { g_plcnt[i] = 0; g_rowsum[i] = 0.f; }
    if (i == 0) { g_acc = 0.0; g_ticket = 0; }
}

// ---------------------------------------------------------------------------
__device__ __forceinline__ void cp16(uint32_t dst, const void* src) {
    asm volatile("cp.async.cg.shared.global [%0], [%1], 16;\n" :: "r"(dst), "l"(src));
}
#define CP_COMMIT() asm volatile("cp.async.commit_group;\n" ::: "memory")
#define CP_WAIT(n)  asm volatile("cp.async.wait_group %0;\n" :: "n"(n) : "memory")

__device__ __forceinline__ void ldsm4(uint32_t& r0, uint32_t& r1, uint32_t& r2, uint32_t& r3,
                                      uint32_t addr) {
    asm volatile("ldmatrix.sync.aligned.m8n8.x4.shared.b16 {%0,%1,%2,%3}, [%4];"
                 : "=r"(r0), "=r"(r1), "=r"(r2), "=r"(r3) : "r"(addr));
}

__device__ __forceinline__ void mma_f16(float c[4], const uint32_t a[4], uint32_t b0, uint32_t b1) {
    asm volatile(
        "mma.sync.aligned.m16n8k16.row.col.f32.f16.f16.f32 "
        "{%0,%1,%2,%3}, {%4,%5,%6,%7}, {%8,%9}, {%0,%1,%2,%3};"
        : "+f"(c[0]), "+f"(c[1]), "+f"(c[2]), "+f"(c[3])
        : "r"(a[0]), "r"(a[1]), "r"(a[2]), "r"(a[3]), "r"(b0), "r"(b1));
}

// ---------------------------------------------------------------------------
// Symmetric-tile fused GEMM+LSE. One upper-triangle 128x128 tile per CTA.
// grid TOT_TILES, block 256 (8 warps: 2M x 4N), warp tile 64x32.
// 3-stage cp.async ring, KC=64, one __syncthreads per k-chunk.
extern __shared__ __align__(16) char dynsmem[];

__global__ void __launch_bounds__(256, 2)
lse_gemm_kernel(const int* __restrict__ lab) {
    int* labA = (int*)(dynsmem + NSTAGE * STAGE_B);
    int* labB = labA + 128;
    const uint32_t smem_base = (uint32_t)__cvta_generic_to_shared(dynsmem);

    // decode upper-triangle tile (I, J), J >= I
    int I = 0, rem = blockIdx.x;
    while (rem >= (NTILE - I)) { rem -= (NTILE - I); I++; }
    const int J = I + rem;
    const int row0 = I * BM;
    const int col0 = J * BM;
    const bool offdiag = (I != J);

    const int tid    = threadIdx.x;
    const int warpid = tid >> 5;
    const int lane   = tid & 31;
    const int warpM0 = (warpid >> 2) * 64;
    const int warpN0 = (warpid & 3) * 32;

    // ldmatrix per-lane geometry (verified R4/R7/R9/R10)
    const int li = lane & 7, lm = lane >> 3;
    const int rA    = warpM0 + li + (lm & 1) * 8;
    const int kAoff = lm >> 1;
    const int nB    = warpN0 + li + (lm >> 1) * 8;
    const int kBoff = lm & 1;
    const int sA    = li;
    const int sB    = li;

    if (tid < 128) labA[tid] = lab[row0 + tid];
    else           labB[tid - 128] = lab[col0 + tid - 128];

    float acc[4][4][4];
#pragma unroll
    for (int mt = 0; mt < 4; mt++)
#pragma unroll
        for (int nt = 0; nt < 4; nt++)
#pragma unroll
            for (int e = 0; e < 4; e++) acc[mt][nt][e] = 0.f;

    auto load_stage = [&](int stage, int kc) {
        const int ke = kc * KC;
        const uint32_t sbase = smem_base + stage * STAGE_B;
#pragma unroll
        for (int half = 0; half < 4; half++) {
            const int c = tid + half * 256;          // 0..1023
            const int row = c >> 3, chk = c & 7;
            const uint32_t doff = (uint32_t)(row * 8 + (chk ^ (row & 7))) * 16;
            const size_t aoff = (size_t)(row0 + row) * DDIM + ke + chk * 8;
            const size_t boff = (size_t)(col0 + row) * DDIM + ke + chk * 8;
            cp16(sbase + 0 * TILE_B + doff, g_Eh + aoff);
            cp16(sbase + 1 * TILE_B + doff, g_Eh + boff);
        }
        CP_COMMIT();
    };

    load_stage(0, 0);
    load_stage(1, 1);

    int stage = 0;
    for (int kc = 0; kc < NKC; kc++) {
        if (kc + 1 < NKC) { CP_WAIT(1); } else { CP_WAIT(0); }
        __syncthreads();

        if (kc + 2 < NKC) {
            int ns = stage + 2; if (ns >= NSTAGE) ns -= NSTAGE;
            load_stage(ns, kc + 2);
        }

        const uint32_t sbase = smem_base + stage * STAGE_B;
#pragma unroll
        for (int kk = 0; kk < 4; kk++) {
            uint32_t a[4][4], b[2][4];
#pragma unroll
            for (int mt = 0; mt < 4; mt++) {
                uint32_t addr = sbase + 0 * TILE_B +
                    (uint32_t)((rA + mt * 16) * 8 + ((kk * 2 + kAoff) ^ sA)) * 16;
                ldsm4(a[mt][0], a[mt][1], a[mt][2], a[mt][3], addr);
            }
#pragma unroll
            for (int np = 0; np < 2; np++) {
                uint32_t addr = sbase + 1 * TILE_B +
                    (uint32_t)((nB + np * 16) * 8 + ((kk * 2 + kBoff) ^ sB)) * 16;
                ldsm4(b[np][0], b[np][1], b[np][2], b[np][3], addr);
            }
#pragma unroll
            for (int mt = 0; mt < 4; mt++)
#pragma unroll
                for (int np = 0; np < 2; np++) {
                    mma_f16(acc[mt][2 * np + 0], a[mt], b[np][0], b[np][1]);
                    mma_f16(acc[mt][2 * np + 1], a[mt], b[np][2], b[np][3]);
                }
        }
        if (++stage >= NSTAGE) stage -= NSTAGE;
    }
    __syncthreads();

    // ---- epilogue: row sums + (off-diag) column sums + same-label scatter ----
    int rlab[8], clab[8];
#pragma unroll
    for (int mt = 0; mt < 4; mt++)
#pragma unroll
        for (int h = 0; h < 2; h++)
            rlab[mt * 2 + h] = labA[warpM0 + mt * 16 + (lane >> 2) + h * 8];
#pragma unroll
    for (int nt = 0; nt < 4; nt++)
#pragma unroll
        for (int j = 0; j < 2; j++)
            clab[nt * 2 + j] = labB[warpN0 + nt * 8 + (lane & 3) * 2 + j];

    float colAcc[8];
#pragma unroll
    for (int i = 0; i < 8; i++) colAcc[i] = 0.f;

#pragma unroll
    for (int mt = 0; mt < 4; mt++)
#pragma unroll
        for (int h = 0; h < 2; h++) {
            const int gr = row0 + warpM0 + mt * 16 + (lane >> 2) + h * 8;
            float s = 0.f;
#pragma unroll
            for (int nt = 0; nt < 4; nt++)
#pragma unroll
                for (int j = 0; j < 2; j++) {
                    const float v = acc[mt][nt][h * 2 + j] * INV_T;
                    const int gc = col0 + warpN0 + nt * 8 + (lane & 3) * 2 + j;
                    if (clab[nt * 2 + j] == rlab[mt * 2 + h]) {
                        if (gc != gr) {
                            int idx = atomicAdd(&g_plcnt[gr], 1);
                            if (idx < PLCAP) g_pl[gr * PLCAP + idx] = v;
                            if (offdiag) {
                                int idc = atomicAdd(&g_plcnt[gc], 1);
                                if (idc < PLCAP) g_pl[gc * PLCAP + idc] = v;
                            }
                        }
                    } else {
                        const float e = __expf(v - LSE_C);
                        s += e;
                        colAcc[nt * 2 + j] += e;
                    }
                }
            s += __shfl_xor_sync(0xffffffffu, s, 1);
            s += __shfl_xor_sync(0xffffffffu, s, 2);
            if ((lane & 3) == 0) atomicAdd(&g_rowsum[gr], s);
        }

    if (offdiag) {
#pragma unroll
        for (int idx = 0; idx < 8; idx++) {
            float cs = colAcc[idx];
            cs += __shfl_xor_sync(0xffffffffu, cs, 4);
            cs += __shfl_xor_sync(0xffffffffu, cs, 8);
            cs += __shfl_xor_sync(0xffffffffu, cs, 16);
            if ((lane >> 2) == 0) {
                const int gc = col0 + warpN0 + (idx >> 1) * 8 + (lane & 3) * 2 + (idx & 1);
                atomicAdd(&g_rowsum[gc], cs);
            }
        }
    }
}

// ---------------------------------------------------------------------------
// One warp per row: base = LSE_C + log(rowsum); sum softplus(base - l).
// Last warp (ticket) finalizes the output — no separate finalize launch.
__global__ void pair_kernel(float* out) {
    const int warp = (blockIdx.x * blockDim.x + threadIdx.x) >> 5;
    const int lane = threadIdx.x & 31;
    if (warp >= BDIM) return;
    int cnt = g_plcnt[warp];
    if (cnt > PLCAP) cnt = PLCAP;
    const float base = LSE_C + __logf(g_rowsum[warp]);
    float rowsum = 0.f;
    for (int t = lane; t < cnt; t += 32) {
        const float l = g_pl[warp * PLCAP + t];
        const float x = base - l;
        // softplus(x), fast-math variant: log1p(e) -> __logf(1+e), e <= 1
        rowsum += (x > 0.f) ? x + __logf(1.f + __expf(-x)) : __logf(1.f + __expf(x));
    }
#pragma unroll
    for (int o = 16; o > 0; o >>= 1) rowsum += __shfl_xor_sync(0xffffffffu, rowsum, o);

    if (lane == 0) {
        if (cnt > 0) atomicAdd(&g_acc, (double)(rowsum / (float)cnt));
        __threadfence();
        const int t = atomicAdd(&g_ticket, 1);
        if (t == BDIM - 1) {
            __threadfence();
            const double total = atomicAdd(&g_acc, 0.0);  // fenced read
            out[0] = (float)(total / (double)BDIM);
        }
    }
}

// ---------------------------------------------------------------------------
extern "C" void kernel_launch(void* const* d_in, const int* in_sizes, int n_in,
                              void* d_out, int out_size) {
    const float* E   = nullptr;
    const int*   lab = nullptr;
    for (int i = 0; i < n_in; i++) {
        if (in_sizes[i] == BDIM * DDIM) E   = (const float*)d_in[i];
        else if (in_sizes[i] == BDIM)   lab = (const int*)d_in[i];
    }
    float* out = (float*)d_out;

    cudaFuncSetAttribute(lse_gemm_kernel,
                         cudaFuncAttributeMaxDynamicSharedMemorySize, SMEM_BYTES);

    convert_kernel<<<(BDIM * DDIM / 4) / 256, 256>>>(E);
    lse_gemm_kernel<<<TOT_TILES, 256, SMEM_BYTES>>>(lab);
    pair_kernel<<<BDIM / 8, 256>>>(out);
}

// round 14
// speedup vs baseline: 1.4278x; 1.0454x over previous
#include <cuda_runtime.h>
#include <cuda_fp16.h>
#include <math.h>
#include <stdint.h>

#define BDIM 8192
#define DDIM 512
#define INV_T (1.0f/0.07f)
#define SHIFT 8.0f                    // LSE shift; max different-label logit ~3.6
#define LOG2E 1.44269504f

#define BM 128
#define KC 64
#define NKC (DDIM/KC)                 // 8
#define NTILE (BDIM/BM)               // 64
#define TOT_TILES (NTILE*(NTILE+1)/2) // 2080
#define PLCAP 256
#define NSTAGE 3
#define GRID_GEMM 304

#define TILE_B (BM*KC*2)              // 16384 B per fp16 tile (128 B/row)
#define STAGE_B (2*TILE_B)            // A + B = 32 KB
#define SMEM_BYTES (NSTAGE*STAGE_B + 1088)

// ---- device scratch ----
__device__ __half g_Eh[BDIM*DDIM];
__device__ float  g_rowsum[BDIM];
__device__ float  g_pl[BDIM*PLCAP];
__device__ int    g_plcnt[BDIM];
__device__ double g_acc;
__device__ int    g_ticket;
__device__ int    g_tile;

// ---------------------------------------------------------------------------
// fp32 -> fp16, fused with state init.
__global__ void convert_kernel(const float* __restrict__ E) {
    int i = blockIdx.x * blockDim.x + threadIdx.x;   // over BDIM*DDIM/4
    float4 v = reinterpret_cast<const float4*>(E)[i];
    __half2* dst = reinterpret_cast<__half2*>(g_Eh) + 2 * i;
    dst[0] = __floats2half2_rn(v.x, v.y);
    dst[1] = __floats2half2_rn(v.z, v.w);
    if (i < BDIM) { g_plcnt[i] = 0; g_rowsum[i] = 0.f; }
    if (i == 0) { g_acc = 0.0; g_ticket = 0; g_tile = 0; }
}

// ---------------------------------------------------------------------------
__device__ __forceinline__ void cp16(uint32_t dst, const void* src) {
    asm volatile("cp.async.cg.shared.global [%0], [%1], 16;\n" :: "r"(dst), "l"(src));
}
#define CP_COMMIT() asm volatile("cp.async.commit_group;\n" ::: "memory")
#define CP_WAIT(n)  asm volatile("cp.async.wait_group %0;\n" :: "n"(n) : "memory")

__device__ __forceinline__ void ldsm4(uint32_t& r0, uint32_t& r1, uint32_t& r2, uint32_t& r3,
                                      uint32_t addr) {
    asm volatile("ldmatrix.sync.aligned.m8n8.x4.shared.b16 {%0,%1,%2,%3}, [%4];"
                 : "=r"(r0), "=r"(r1), "=r"(r2), "=r"(r3) : "r"(addr));
}

__device__ __forceinline__ void mma_f16(float c[4], const uint32_t a[4], uint32_t b0, uint32_t b1) {
    asm volatile(
        "mma.sync.aligned.m16n8k16.row.col.f32.f16.f16.f32 "
        "{%0,%1,%2,%3}, {%4,%5,%6,%7}, {%8,%9}, {%0,%1,%2,%3};"
        : "+f"(c[0]), "+f"(c[1]), "+f"(c[2]), "+f"(c[3])
        : "r"(a[0]), "r"(a[1]), "r"(a[2]), "r"(a[3]), "r"(b0), "r"(b1));
}

// ---------------------------------------------------------------------------
// Persistent symmetric-tile fused GEMM+LSE. Tickets over upper-triangle tiles.
// grid GRID_GEMM, block 256 (8 warps: 2M x 4N), warp tile 64x32, occ 2.
extern __shared__ __align__(16) char dynsmem[];

__global__ void __launch_bounds__(256, 2)
lse_gemm_kernel(const int* __restrict__ lab) {
    int* labA = (int*)(dynsmem + NSTAGE * STAGE_B);
    int* labB = labA + 128;
    int* sTicket = labB + 128;
    const uint32_t smem_base = (uint32_t)__cvta_generic_to_shared(dynsmem);

    const int tid    = threadIdx.x;
    const int warpid = tid >> 5;
    const int lane   = tid & 31;
    const int warpM0 = (warpid >> 2) * 64;
    const int warpN0 = (warpid & 3) * 32;

    // ldmatrix per-lane geometry (verified R4/R7/R9/R10)
    const int li = lane & 7, lm = lane >> 3;
    const int rA    = warpM0 + li + (lm & 1) * 8;
    const int kAoff = lm >> 1;
    const int nB    = warpN0 + li + (lm >> 1) * 8;
    const int kBoff = lm & 1;

    for (;;) {
        if (tid == 0) *sTicket = atomicAdd(&g_tile, 1);
        __syncthreads();
        const int tk = *sTicket;
        if (tk >= TOT_TILES) return;

        // decode upper-triangle tile (I, J), J >= I
        int I = 0, rem = tk;
        while (rem >= (NTILE - I)) { rem -= (NTILE - I); I++; }
        const int J = I + rem;
        const int row0 = I * BM;
        const int col0 = J * BM;
        const bool offdiag = (I != J);

        if (tid < 128) labA[tid] = lab[row0 + tid];
        else           labB[tid - 128] = lab[col0 + tid - 128];

        float acc[4][4][4];
#pragma unroll
        for (int mt = 0; mt < 4; mt++)
#pragma unroll
            for (int nt = 0; nt < 4; nt++)
#pragma unroll
                for (int e = 0; e < 4; e++) acc[mt][nt][e] = 0.f;

        auto load_stage = [&](int stage, int kc) {
            const int ke = kc * KC;
            const uint32_t sbase = smem_base + stage * STAGE_B;
#pragma unroll
            for (int half = 0; half < 4; half++) {
                const int c = tid + half * 256;          // 0..1023
                const int row = c >> 3, chk = c & 7;
                const uint32_t doff = (uint32_t)(row * 8 + (chk ^ (row & 7))) * 16;
                const size_t aoff = (size_t)(row0 + row) * DDIM + ke + chk * 8;
                const size_t boff = (size_t)(col0 + row) * DDIM + ke + chk * 8;
                cp16(sbase + 0 * TILE_B + doff, g_Eh + aoff);
                cp16(sbase + 1 * TILE_B + doff, g_Eh + boff);
            }
            CP_COMMIT();
        };

        load_stage(0, 0);
        load_stage(1, 1);

        int stage = 0;
        for (int kc = 0; kc < NKC; kc++) {
            if (kc + 1 < NKC) { CP_WAIT(1); } else { CP_WAIT(0); }
            __syncthreads();

            if (kc + 2 < NKC) {
                int ns = stage + 2; if (ns >= NSTAGE) ns -= NSTAGE;
                load_stage(ns, kc + 2);
            }

            const uint32_t sbase = smem_base + stage * STAGE_B;
#pragma unroll
            for (int kk = 0; kk < 4; kk++) {
                uint32_t a[4][4], b[2][4];
#pragma unroll
                for (int mt = 0; mt < 4; mt++) {
                    uint32_t addr = sbase + 0 * TILE_B +
                        (uint32_t)((rA + mt * 16) * 8 + ((kk * 2 + kAoff) ^ li)) * 16;
                    ldsm4(a[mt][0], a[mt][1], a[mt][2], a[mt][3], addr);
                }
#pragma unroll
                for (int np = 0; np < 2; np++) {
                    uint32_t addr = sbase + 1 * TILE_B +
                        (uint32_t)((nB + np * 16) * 8 + ((kk * 2 + kBoff) ^ li)) * 16;
                    ldsm4(b[np][0], b[np][1], b[np][2], b[np][3], addr);
                }
#pragma unroll
                for (int mt = 0; mt < 4; mt++)
#pragma unroll
                    for (int np = 0; np < 2; np++) {
                        mma_f16(acc[mt][2 * np + 0], a[mt], b[np][0], b[np][1]);
                        mma_f16(acc[mt][2 * np + 1], a[mt], b[np][2], b[np][3]);
                    }
            }
            if (++stage >= NSTAGE) stage -= NSTAGE;
        }
        __syncthreads();

        // ---- epilogue: f16x2 exp, row/col sums, same-label scatter ----
        int rlab[8], clab[8];
#pragma unroll
        for (int mt = 0; mt < 4; mt++)
#pragma unroll
            for (int h = 0; h < 2; h++)
                rlab[mt * 2 + h] = labA[warpM0 + mt * 16 + (lane >> 2) + h * 8];
#pragma unroll
        for (int nt = 0; nt < 4; nt++)
#pragma unroll
            for (int j = 0; j < 2; j++)
                clab[nt * 2 + j] = labB[warpN0 + nt * 8 + (lane & 3) * 2 + j];

        __half2 colAcc[4];
#pragma unroll
        for (int i = 0; i < 4; i++) colAcc[i] = __floats2half2_rn(0.f, 0.f);

        const float K1 = INV_T * LOG2E;      // acc -> log2-domain logits
        const float S2 = SHIFT * LOG2E;

#pragma unroll
        for (int mt = 0; mt < 4; mt++)
#pragma unroll
            for (int h = 0; h < 2; h++) {
                const int gr = row0 + warpM0 + mt * 16 + (lane >> 2) + h * 8;
                const int rl = rlab[mt * 2 + h];
                __half2 rowAcc = __floats2half2_rn(0.f, 0.f);
#pragma unroll
                for (int nt = 0; nt < 4; nt++) {
                    float a0 = acc[mt][nt][h * 2 + 0];
                    float a1 = acc[mt][nt][h * 2 + 1];
                    float u0 = fmaf(a0, K1, -S2);
                    float u1 = fmaf(a1, K1, -S2);
                    if (clab[nt * 2 + 0] == rl) {
                        const int gc = col0 + warpN0 + nt * 8 + (lane & 3) * 2;
                        if (gc != gr) {
                            const float v = a0 * INV_T;
                            int idx = atomicAdd(&g_plcnt[gr], 1);
                            if (idx < PLCAP) g_pl[gr * PLCAP + idx] = v;
                            if (offdiag) {
                                int idc = atomicAdd(&g_plcnt[gc], 1);
                                if (idc < PLCAP) g_pl[gc * PLCAP + idc] = v;
                            }
                        }
                        u0 = -60.f;
                    }
                    if (clab[nt * 2 + 1] == rl) {
                        const int gc = col0 + warpN0 + nt * 8 + (lane & 3) * 2 + 1;
                        if (gc != gr) {
                            const float v = a1 * INV_T;
                            int idx = atomicAdd(&g_plcnt[gr], 1);
                            if (idx < PLCAP) g_pl[gr * PLCAP + idx] = v;
                            if (offdiag) {
                                int idc = atomicAdd(&g_plcnt[gc], 1);
                                if (idc < PLCAP) g_pl[gc * PLCAP + idc] = v;
                            }
                        }
                        u1 = -60.f;
                    }
                    const __half2 e = h2exp2(__floats2half2_rn(u0, u1));
                    rowAcc = __hadd2(rowAcc, e);
                    colAcc[nt] = __hadd2(colAcc[nt], e);
                }
                const float2 rf = __half22float2(rowAcc);
                float s = rf.x + rf.y;
                s += __shfl_xor_sync(0xffffffffu, s, 1);
                s += __shfl_xor_sync(0xffffffffu, s, 2);
                if ((lane & 3) == 0) atomicAdd(&g_rowsum[gr], s);
            }

        if (offdiag) {
#pragma unroll
            for (int nt = 0; nt < 4; nt++) {
                uint32_t c = *reinterpret_cast<uint32_t*>(&colAcc[nt]);
                __half2 hc = colAcc[nt];
#pragma unroll
                for (int o = 4; o <= 16; o <<= 1) {
                    uint32_t pc = __shfl_xor_sync(0xffffffffu, *reinterpret_cast<uint32_t*>(&hc), o);
                    hc = __hadd2(hc, *reinterpret_cast<__half2*>(&pc));
                }
                (void)c;
                if ((lane >> 2) == 0) {
                    const float2 f = __half22float2(hc);
                    const int gc0 = col0 + warpN0 + nt * 8 + (lane & 3) * 2;
                    atomicAdd(&g_rowsum[gc0], f.x);
                    atomicAdd(&g_rowsum[gc0 + 1], f.y);
                }
            }
        }
        __syncthreads();   // protect smem labels/ticket before next tile
    }
}

// ---------------------------------------------------------------------------
// One warp per row: base = SHIFT + log(rowsum); sum softplus(base - l).
// Last warp (ticket) finalizes the output.
__global__ void pair_kernel(float* out) {
    const int warp = (blockIdx.x * blockDim.x + threadIdx.x) >> 5;
    const int lane = threadIdx.x & 31;
    if (warp >= BDIM) return;
    int cnt = g_plcnt[warp];
    if (cnt > PLCAP) cnt = PLCAP;
    const float base = SHIFT + __logf(g_rowsum[warp]);
    float rowsum = 0.f;
    for (int t = lane; t < cnt; t += 32) {
        const float l = g_pl[warp * PLCAP + t];
        const float x = base - l;
        rowsum += (x > 0.f) ? x + __logf(1.f + __expf(-x)) : __logf(1.f + __expf(x));
    }
#pragma unroll
    for (int o = 16; o > 0; o >>= 1) rowsum += __shfl_xor_sync(0xffffffffu, rowsum, o);

    if (lane == 0) {
        if (cnt > 0) atomicAdd(&g_acc, (double)(rowsum / (float)cnt));
        __threadfence();
        const int t = atomicAdd(&g_ticket, 1);
        if (t == BDIM - 1) {
            __threadfence();
            const double total = atomicAdd(&g_acc, 0.0);
            out[0] = (float)(total / (double)BDIM);
        }
    }
}

// ---------------------------------------------------------------------------
extern "C" void kernel_launch(void* const* d_in, const int* in_sizes, int n_in,
                              void* d_out, int out_size) {
    const float* E   = nullptr;
    const int*   lab = nullptr;
    for (int i = 0; i < n_in; i++) {
        if (in_sizes[i] == BDIM * DDIM) E   = (const float*)d_in[i];
        else if (in_sizes[i] == BDIM)   lab = (const int*)d_in[i];
    }
    float* out = (float*)d_out;

    cudaFuncSetAttribute(lse_gemm_kernel,
                         cudaFuncAttributeMaxDynamicSharedMemorySize, SMEM_BYTES);

    convert_kernel<<<(BDIM * DDIM / 4) / 256, 256>>>(E);
    lse_gemm_kernel<<<GRID_GEMM, 256, SMEM_BYTES>>>(lab);
    pair_kernel<<<BDIM / 8, 256>>>(out);
}

// round 15
// speedup vs baseline: 1.4315x; 1.0026x over previous
#include <cuda_runtime.h>
#include <cuda_fp16.h>
#include <math.h>
#include <stdint.h>

#define BDIM 8192
#define DDIM 512
#define INV_T (1.0f/0.07f)
#define SHIFT 8.0f                    // LSE shift; max different-label logit ~3.6
#define LOG2E 1.44269504f

#define BM 128
#define KC 64
#define NKC (DDIM/KC)                 // 8
#define NTILE (BDIM/BM)               // 64
#define TOT_TILES (NTILE*(NTILE+1)/2) // 2080
#define PLCAP 256
#define NSTAGE 3
#define GRID_GEMM 304

#define TILE_B (BM*KC*2)              // 16384 B per fp16 tile (128 B/row)
#define STAGE_B (2*TILE_B)            // A + B = 32 KB
#define SMEM_BYTES (NSTAGE*STAGE_B + 1088)

// ---- device scratch ----
__device__ __half g_Eh[BDIM*DDIM];
__device__ float  g_rowsum[BDIM];
__device__ float  g_pl[BDIM*PLCAP];
__device__ int    g_plcnt[BDIM];
__device__ double g_acc;
__device__ int    g_ticket;
__device__ int    g_tile;

// ---------------------------------------------------------------------------
// fp32 -> fp16, fused with state init.
__global__ void convert_kernel(const float* __restrict__ E) {
    int i = blockIdx.x * blockDim.x + threadIdx.x;   // over BDIM*DDIM/4
    float4 v = reinterpret_cast<const float4*>(E)[i];
    __half2* dst = reinterpret_cast<__half2*>(g_Eh) + 2 * i;
    dst[0] = __floats2half2_rn(v.x, v.y);
    dst[1] = __floats2half2_rn(v.z, v.w);
    if (i < BDIM) { g_plcnt[i] = 0; g_rowsum[i] = 0.f; }
    if (i == 0) { g_acc = 0.0; g_ticket = 0; g_tile = 0; }
}

// ---------------------------------------------------------------------------
__device__ __forceinline__ void cp16(uint32_t dst, const void* src) {
    asm volatile("cp.async.cg.shared.global [%0], [%1], 16;\n" :: "r"(dst), "l"(src));
}
#define CP_COMMIT() asm volatile("cp.async.commit_group;\n" ::: "memory")
#define CP_WAIT(n)  asm volatile("cp.async.wait_group %0;\n" :: "n"(n) : "memory")

__device__ __forceinline__ void ldsm4(uint32_t& r0, uint32_t& r1, uint32_t& r2, uint32_t& r3,
                                      uint32_t addr) {
    asm volatile("ldmatrix.sync.aligned.m8n8.x4.shared.b16 {%0,%1,%2,%3}, [%4];"
                 : "=r"(r0), "=r"(r1), "=r"(r2), "=r"(r3) : "r"(addr));
}

// fp16 accumulator MMA: D,C are 2x f16x2 regs (c0,c1 | c2,c3)
__device__ __forceinline__ void mma_f16acc(uint32_t c[2], const uint32_t a[4],
                                           uint32_t b0, uint32_t b1) {
    asm volatile(
        "mma.sync.aligned.m16n8k16.row.col.f16.f16.f16.f16 "
        "{%0,%1}, {%2,%3,%4,%5}, {%6,%7}, {%0,%1};"
        : "+r"(c[0]), "+r"(c[1])
        : "r"(a[0]), "r"(a[1]), "r"(a[2]), "r"(a[3]), "r"(b0), "r"(b1));
}

// ---------------------------------------------------------------------------
// Persistent symmetric-tile fused GEMM+LSE. Tickets over upper-triangle tiles.
// grid GRID_GEMM, block 256 (8 warps: 2M x 4N), warp tile 64x32, occ 2.
extern __shared__ __align__(16) char dynsmem[];

__global__ void __launch_bounds__(256, 2)
lse_gemm_kernel(const int* __restrict__ lab) {
    int* labA = (int*)(dynsmem + NSTAGE * STAGE_B);
    int* labB = labA + 128;
    int* sTicket = labB + 128;
    const uint32_t smem_base = (uint32_t)__cvta_generic_to_shared(dynsmem);

    const int tid    = threadIdx.x;
    const int warpid = tid >> 5;
    const int lane   = tid & 31;
    const int warpM0 = (warpid >> 2) * 64;
    const int warpN0 = (warpid & 3) * 32;

    // ldmatrix per-lane geometry (verified R4/R7/R9/R10)
    const int li = lane & 7, lm = lane >> 3;
    const int rA    = warpM0 + li + (lm & 1) * 8;
    const int kAoff = lm >> 1;
    const int nB    = warpN0 + li + (lm >> 1) * 8;
    const int kBoff = lm & 1;

    for (;;) {
        if (tid == 0) *sTicket = atomicAdd(&g_tile, 1);
        __syncthreads();
        const int tk = *sTicket;
        if (tk >= TOT_TILES) return;

        // decode upper-triangle tile (I, J), J >= I
        int I = 0, rem = tk;
        while (rem >= (NTILE - I)) { rem -= (NTILE - I); I++; }
        const int J = I + rem;
        const int row0 = I * BM;
        const int col0 = J * BM;
        const bool offdiag = (I != J);

        if (tid < 128) labA[tid] = lab[row0 + tid];
        else           labB[tid - 128] = lab[col0 + tid - 128];

        uint32_t acc[4][4][2];     // f16x2 accumulators: [mt][nt][h], lo=j0 hi=j1
#pragma unroll
        for (int mt = 0; mt < 4; mt++)
#pragma unroll
            for (int nt = 0; nt < 4; nt++) { acc[mt][nt][0] = 0u; acc[mt][nt][1] = 0u; }

        auto load_stage = [&](int stage, int kc) {
            const int ke = kc * KC;
            const uint32_t sbase = smem_base + stage * STAGE_B;
#pragma unroll
            for (int half = 0; half < 4; half++) {
                const int c = tid + half * 256;          // 0..1023
                const int row = c >> 3, chk = c & 7;
                const uint32_t doff = (uint32_t)(row * 8 + (chk ^ (row & 7))) * 16;
                const size_t aoff = (size_t)(row0 + row) * DDIM + ke + chk * 8;
                const size_t boff = (size_t)(col0 + row) * DDIM + ke + chk * 8;
                cp16(sbase + 0 * TILE_B + doff, g_Eh + aoff);
                cp16(sbase + 1 * TILE_B + doff, g_Eh + boff);
            }
            CP_COMMIT();
        };

        load_stage(0, 0);
        load_stage(1, 1);

        int stage = 0;
        for (int kc = 0; kc < NKC; kc++) {
            if (kc + 1 < NKC) { CP_WAIT(1); } else { CP_WAIT(0); }
            __syncthreads();

            if (kc + 2 < NKC) {
                int ns = stage + 2; if (ns >= NSTAGE) ns -= NSTAGE;
                load_stage(ns, kc + 2);
            }

            const uint32_t sbase = smem_base + stage * STAGE_B;
#pragma unroll
            for (int kk = 0; kk < 4; kk++) {
                uint32_t a[4][4], b[2][4];
#pragma unroll
                for (int mt = 0; mt < 4; mt++) {
                    uint32_t addr = sbase + 0 * TILE_B +
                        (uint32_t)((rA + mt * 16) * 8 + ((kk * 2 + kAoff) ^ li)) * 16;
                    ldsm4(a[mt][0], a[mt][1], a[mt][2], a[mt][3], addr);
                }
#pragma unroll
                for (int np = 0; np < 2; np++) {
                    uint32_t addr = sbase + 1 * TILE_B +
                        (uint32_t)((nB + np * 16) * 8 + ((kk * 2 + kBoff) ^ li)) * 16;
                    ldsm4(b[np][0], b[np][1], b[np][2], b[np][3], addr);
                }
#pragma unroll
                for (int mt = 0; mt < 4; mt++)
#pragma unroll
                    for (int np = 0; np < 2; np++) {
                        mma_f16acc(acc[mt][2 * np + 0], a[mt], b[np][0], b[np][1]);
                        mma_f16acc(acc[mt][2 * np + 1], a[mt], b[np][2], b[np][3]);
                    }
            }
            if (++stage >= NSTAGE) stage -= NSTAGE;
        }
        __syncthreads();

        // ---- epilogue: f16x2 exp, row/col sums, same-label scatter ----
        int rlab[8], clab[8];
#pragma unroll
        for (int mt = 0; mt < 4; mt++)
#pragma unroll
            for (int h = 0; h < 2; h++)
                rlab[mt * 2 + h] = labA[warpM0 + mt * 16 + (lane >> 2) + h * 8];
#pragma unroll
        for (int nt = 0; nt < 4; nt++)
#pragma unroll
            for (int j = 0; j < 2; j++)
                clab[nt * 2 + j] = labB[warpN0 + nt * 8 + (lane & 3) * 2 + j];

        __half2 colAcc[4];
#pragma unroll
        for (int i = 0; i < 4; i++) colAcc[i] = __floats2half2_rn(0.f, 0.f);

        const float K1 = INV_T * LOG2E;      // dot -> log2-domain logits
        const float S2 = SHIFT * LOG2E;

#pragma unroll
        for (int mt = 0; mt < 4; mt++)
#pragma unroll
            for (int h = 0; h < 2; h++) {
                const int gr = row0 + warpM0 + mt * 16 + (lane >> 2) + h * 8;
                const int rl = rlab[mt * 2 + h];
                __half2 rowAcc = __floats2half2_rn(0.f, 0.f);
#pragma unroll
                for (int nt = 0; nt < 4; nt++) {
                    uint32_t reg = acc[mt][nt][h];
                    const float2 f = __half22float2(*reinterpret_cast<__half2*>(&reg));
                    const float a0 = f.x, a1 = f.y;
                    float u0 = fmaf(a0, K1, -S2);
                    float u1 = fmaf(a1, K1, -S2);
                    if (clab[nt * 2 + 0] == rl) {
                        const int gc = col0 + warpN0 + nt * 8 + (lane & 3) * 2;
                        if (gc != gr) {
                            const float v = a0 * INV_T;
                            int idx = atomicAdd(&g_plcnt[gr], 1);
                            if (idx < PLCAP) g_pl[gr * PLCAP + idx] = v;
                            if (offdiag) {
                                int idc = atomicAdd(&g_plcnt[gc], 1);
                                if (idc < PLCAP) g_pl[gc * PLCAP + idc] = v;
                            }
                        }
                        u0 = -60.f;
                    }
                    if (clab[nt * 2 + 1] == rl) {
                        const int gc = col0 + warpN0 + nt * 8 + (lane & 3) * 2 + 1;
                        if (gc != gr) {
                            const float v = a1 * INV_T;
                            int idx = atomicAdd(&g_plcnt[gr], 1);
                            if (idx < PLCAP) g_pl[gr * PLCAP + idx] = v;
                            if (offdiag) {
                                int idc = atomicAdd(&g_plcnt[gc], 1);
                                if (idc < PLCAP) g_pl[gc * PLCAP + idc] = v;
                            }
                        }
                        u1 = -60.f;
                    }
                    const __half2 e = h2exp2(__floats2half2_rn(u0, u1));
                    rowAcc = __hadd2(rowAcc, e);
                    colAcc[nt] = __hadd2(colAcc[nt], e);
                }
                const float2 rf = __half22float2(rowAcc);
                float s = rf.x + rf.y;
                s += __shfl_xor_sync(0xffffffffu, s, 1);
                s += __shfl_xor_sync(0xffffffffu, s, 2);
                if ((lane & 3) == 0) atomicAdd(&g_rowsum[gr], s);
            }

        if (offdiag) {
#pragma unroll
            for (int nt = 0; nt < 4; nt++) {
                __half2 hc = colAcc[nt];
#pragma unroll
                for (int o = 4; o <= 16; o <<= 1) {
                    uint32_t u = *reinterpret_cast<uint32_t*>(&hc);
                    uint32_t pc = __shfl_xor_sync(0xffffffffu, u, o);
                    hc = __hadd2(hc, *reinterpret_cast<__half2*>(&pc));
                }
                if ((lane >> 2) == 0) {
                    const float2 f = __half22float2(hc);
                    const int gc0 = col0 + warpN0 + nt * 8 + (lane & 3) * 2;
                    atomicAdd(&g_rowsum[gc0], f.x);
                    atomicAdd(&g_rowsum[gc0 + 1], f.y);
                }
            }
        }
        __syncthreads();   // protect smem labels/ticket before next tile
    }
}

// ---------------------------------------------------------------------------
// One warp per row: base = SHIFT + log(rowsum); sum softplus(base - l).
// Last warp (ticket) finalizes the output.
__global__ void pair_kernel(float* out) {
    const int warp = (blockIdx.x * blockDim.x + threadIdx.x) >> 5;
    const int lane = threadIdx.x & 31;
    if (warp >= BDIM) return;
    int cnt = g_plcnt[warp];
    if (cnt > PLCAP) cnt = PLCAP;
    const float base = SHIFT + __logf(g_rowsum[warp]);
    float rowsum = 0.f;
    for (int t = lane; t < cnt; t += 32) {
        const float l = g_pl[warp * PLCAP + t];
        const float x = base - l;
        rowsum += (x > 0.f) ? x + __logf(1.f + __expf(-x)) : __logf(1.f + __expf(x));
    }
#pragma unroll
    for (int o = 16; o > 0; o >>= 1) rowsum += __shfl_xor_sync(0xffffffffu, rowsum, o);

    if (lane == 0) {
        if (cnt > 0) atomicAdd(&g_acc, (double)(rowsum / (float)cnt));
        __threadfence();
        const int t = atomicAdd(&g_ticket, 1);
        if (t == BDIM - 1) {
            __threadfence();
            const double total = atomicAdd(&g_acc, 0.0);
            out[0] = (float)(total / (double)BDIM);
        }
    }
}

// ---------------------------------------------------------------------------
extern "C" void kernel_launch(void* const* d_in, const int* in_sizes, int n_in,
                              void* d_out, int out_size) {
    const float* E   = nullptr;
    const int*   lab = nullptr;
    for (int i = 0; i < n_in; i++) {
        if (in_sizes[i] == BDIM * DDIM) E   = (const float*)d_in[i];
        else if (in_sizes[i] == BDIM)   lab = (const int*)d_in[i];
    }
    float* out = (float*)d_out;

    cudaFuncSetAttribute(lse_gemm_kernel,
                         cudaFuncAttributeMaxDynamicSharedMemorySize, SMEM_BYTES);

    convert_kernel<<<(BDIM * DDIM / 4) / 256, 256>>>(E);
    lse_gemm_kernel<<<GRID_GEMM, 256, SMEM_BYTES>>>(lab);
    pair_kernel<<<BDIM / 8, 256>>>(out);
}

// round 16
// speedup vs baseline: 1.7149x; 1.1980x over previous
#include <cuda_runtime.h>
#include <cuda_fp16.h>
#include <math.h>
#include <stdint.h>

#define BDIM 8192
#define DDIM 512
#define INV_T (1.0f/0.07f)
#define SHIFT 8.0f                    // LSE shift; max different-label logit ~3.6
#define LOG2E 1.44269504f

#define BM 128
#define KC 64
#define NKC (DDIM/KC)                 // 8
#define NTILE (BDIM/BM)               // 64
#define TOT_TILES (NTILE*(NTILE+1)/2) // 2080
#define PLCAP 256
#define NSTAGE 2
#define GRID_GEMM 444                 // 148 SMs x occ 3, persistent

#define TILE_B (BM*KC*2)              // 16384 B per fp16 tile (128 B/row)
#define STAGE_B (2*TILE_B)            // A + B = 32 KB
#define SMEM_BYTES (NSTAGE*STAGE_B + 1088)   // ~66.6 KB -> 3 CTAs/SM

// ---- device scratch ----
__device__ __half g_Eh[BDIM*DDIM];
__device__ float  g_rowsum[BDIM];
__device__ float  g_pl[BDIM*PLCAP];
__device__ int    g_plcnt[BDIM];
__device__ double g_acc;
__device__ int    g_ticket;
__device__ int    g_tile;

// ---------------------------------------------------------------------------
// fp32 -> fp16, fused with state init.
__global__ void convert_kernel(const float* __restrict__ E) {
    int i = blockIdx.x * blockDim.x + threadIdx.x;   // over BDIM*DDIM/4
    float4 v = reinterpret_cast<const float4*>(E)[i];
    __half2* dst = reinterpret_cast<__half2*>(g_Eh) + 2 * i;
    dst[0] = __floats2half2_rn(v.x, v.y);
    dst[1] = __floats2half2_rn(v.z, v.w);
    if (i < BDIM) { g_plcnt[i] = 0; g_rowsum[i] = 0.f; }
    if (i == 0) { g_acc = 0.0; g_ticket = 0; g_tile = 0; }
}

// ---------------------------------------------------------------------------
__device__ __forceinline__ void cp16(uint32_t dst, const void* src) {
    asm volatile("cp.async.cg.shared.global [%0], [%1], 16;\n" :: "r"(dst), "l"(src));
}
#define CP_COMMIT() asm volatile("cp.async.commit_group;\n" ::: "memory")
#define CP_WAIT(n)  asm volatile("cp.async.wait_group %0;\n" :: "n"(n) : "memory")

__device__ __forceinline__ void ldsm4(uint32_t& r0, uint32_t& r1, uint32_t& r2, uint32_t& r3,
                                      uint32_t addr) {
    asm volatile("ldmatrix.sync.aligned.m8n8.x4.shared.b16 {%0,%1,%2,%3}, [%4];"
                 : "=r"(r0), "=r"(r1), "=r"(r2), "=r"(r3) : "r"(addr));
}

// fp16 accumulator MMA: D,C are 2x f16x2 regs
__device__ __forceinline__ void mma_f16acc(uint32_t c[2], const uint32_t a[4],
                                           uint32_t b0, uint32_t b1) {
    asm volatile(
        "mma.sync.aligned.m16n8k16.row.col.f16.f16.f16.f16 "
        "{%0,%1}, {%2,%3,%4,%5}, {%6,%7}, {%0,%1};"
        : "+r"(c[0]), "+r"(c[1])
        : "r"(a[0]), "r"(a[1]), "r"(a[2]), "r"(a[3]), "r"(b0), "r"(b1));
}

// ---------------------------------------------------------------------------
// Persistent symmetric-tile fused GEMM+LSE. Tickets over upper-triangle tiles.
// grid GRID_GEMM, block 256 (8 warps: 2M x 4N), warp tile 64x32, occ 3.
extern __shared__ __align__(16) char dynsmem[];

__global__ void __launch_bounds__(256, 3)
lse_gemm_kernel(const int* __restrict__ lab) {
    int* labA = (int*)(dynsmem + NSTAGE * STAGE_B);
    int* labB = labA + 128;
    int* sTicket = labB + 128;
    const uint32_t smem_base = (uint32_t)__cvta_generic_to_shared(dynsmem);

    const int tid    = threadIdx.x;
    const int warpid = tid >> 5;
    const int lane   = tid & 31;
    const int warpM0 = (warpid >> 2) * 64;
    const int warpN0 = (warpid & 3) * 32;

    // ldmatrix per-lane geometry (verified R4..R15)
    const int li = lane & 7, lm = lane >> 3;
    const int rA    = warpM0 + li + (lm & 1) * 8;
    const int kAoff = lm >> 1;
    const int nB    = warpN0 + li + (lm >> 1) * 8;
    const int kBoff = lm & 1;

    for (;;) {
        if (tid == 0) *sTicket = atomicAdd(&g_tile, 1);
        __syncthreads();
        const int tk = *sTicket;
        if (tk >= TOT_TILES) return;

        // decode upper-triangle tile (I, J), J >= I
        int I = 0, rem = tk;
        while (rem >= (NTILE - I)) { rem -= (NTILE - I); I++; }
        const int J = I + rem;
        const int row0 = I * BM;
        const int col0 = J * BM;
        const bool offdiag = (I != J);

        if (tid < 128) labA[tid] = lab[row0 + tid];
        else           labB[tid - 128] = lab[col0 + tid - 128];

        uint32_t acc[4][4][2];     // f16x2 accumulators
#pragma unroll
        for (int mt = 0; mt < 4; mt++)
#pragma unroll
            for (int nt = 0; nt < 4; nt++) { acc[mt][nt][0] = 0u; acc[mt][nt][1] = 0u; }

        auto load_stage = [&](int stage, int kc) {
            const int ke = kc * KC;
            const uint32_t sbase = smem_base + stage * STAGE_B;
#pragma unroll
            for (int half = 0; half < 4; half++) {
                const int c = tid + half * 256;          // 0..1023
                const int row = c >> 3, chk = c & 7;
                const uint32_t doff = (uint32_t)(row * 8 + (chk ^ (row & 7))) * 16;
                const size_t aoff = (size_t)(row0 + row) * DDIM + ke + chk * 8;
                const size_t boff = (size_t)(col0 + row) * DDIM + ke + chk * 8;
                cp16(sbase + 0 * TILE_B + doff, g_Eh + aoff);
                cp16(sbase + 1 * TILE_B + doff, g_Eh + boff);
            }
            CP_COMMIT();
        };

        load_stage(0, 0);
        load_stage(1, 1);

        int stage = 0;
        for (int kc = 0; kc < NKC; kc++) {
            if (kc + 1 < NKC) { CP_WAIT(1); } else { CP_WAIT(0); }
            __syncthreads();

            const uint32_t sbase = smem_base + stage * STAGE_B;
#pragma unroll
            for (int kk = 0; kk < 4; kk++) {
                uint32_t a[4][4], b[2][4];
#pragma unroll
                for (int mt = 0; mt < 4; mt++) {
                    uint32_t addr = sbase + 0 * TILE_B +
                        (uint32_t)((rA + mt * 16) * 8 + ((kk * 2 + kAoff) ^ li)) * 16;
                    ldsm4(a[mt][0], a[mt][1], a[mt][2], a[mt][3], addr);
                }
#pragma unroll
                for (int np = 0; np < 2; np++) {
                    uint32_t addr = sbase + 1 * TILE_B +
                        (uint32_t)((nB + np * 16) * 8 + ((kk * 2 + kBoff) ^ li)) * 16;
                    ldsm4(b[np][0], b[np][1], b[np][2], b[np][3], addr);
                }
#pragma unroll
                for (int mt = 0; mt < 4; mt++)
#pragma unroll
                    for (int np = 0; np < 2; np++) {
                        mma_f16acc(acc[mt][2 * np + 0], a[mt], b[np][0], b[np][1]);
                        mma_f16acc(acc[mt][2 * np + 1], a[mt], b[np][2], b[np][3]);
                    }
            }
            // next prefetch AFTER compute: with 2 stages, buffer `stage` is the
            // destination for kc+2; it is free only once this kc's compute is done.
            __syncthreads();
            if (kc + 2 < NKC) load_stage(stage, kc + 2);
            stage ^= 1;
        }

        // ---- epilogue: f16x2 exp, row/col sums, same-label scatter ----
        int rlab[8], clab[8];
#pragma unroll
        for (int mt = 0; mt < 4; mt++)
#pragma unroll
            for (int h = 0; h < 2; h++)
                rlab[mt * 2 + h] = labA[warpM0 + mt * 16 + (lane >> 2) + h * 8];
#pragma unroll
        for (int nt = 0; nt < 4; nt++)
#pragma unroll
            for (int j = 0; j < 2; j++)
                clab[nt * 2 + j] = labB[warpN0 + nt * 8 + (lane & 3) * 2 + j];

        __half2 colAcc[4];
#pragma unroll
        for (int i = 0; i < 4; i++) colAcc[i] = __floats2half2_rn(0.f, 0.f);

        const float K1 = INV_T * LOG2E;
        const float S2 = SHIFT * LOG2E;

#pragma unroll
        for (int mt = 0; mt < 4; mt++)
#pragma unroll
            for (int h = 0; h < 2; h++) {
                const int gr = row0 + warpM0 + mt * 16 + (lane >> 2) + h * 8;
                const int rl = rlab[mt * 2 + h];
                __half2 rowAcc = __floats2half2_rn(0.f, 0.f);
#pragma unroll
                for (int nt = 0; nt < 4; nt++) {
                    uint32_t reg = acc[mt][nt][h];
                    const float2 f = __half22float2(*reinterpret_cast<__half2*>(&reg));
                    const float a0 = f.x, a1 = f.y;
                    float u0 = fmaf(a0, K1, -S2);
                    float u1 = fmaf(a1, K1, -S2);
                    if (clab[nt * 2 + 0] == rl) {
                        const int gc = col0 + warpN0 + nt * 8 + (lane & 3) * 2;
                        if (gc != gr) {
                            const float v = a0 * INV_T;
                            int idx = atomicAdd(&g_plcnt[gr], 1);
                            if (idx < PLCAP) g_pl[gr * PLCAP + idx] = v;
                            if (offdiag) {
                                int idc = atomicAdd(&g_plcnt[gc], 1);
                                if (idc < PLCAP) g_pl[gc * PLCAP + idc] = v;
                            }
                        }
                        u0 = -60.f;
                    }
                    if (clab[nt * 2 + 1] == rl) {
                        const int gc = col0 + warpN0 + nt * 8 + (lane & 3) * 2 + 1;
                        if (gc != gr) {
                            const float v = a1 * INV_T;
                            int idx = atomicAdd(&g_plcnt[gr], 1);
                            if (idx < PLCAP) g_pl[gr * PLCAP + idx] = v;
                            if (offdiag) {
                                int idc = atomicAdd(&g_plcnt[gc], 1);
                                if (idc < PLCAP) g_pl[gc * PLCAP + idc] = v;
                            }
                        }
                        u1 = -60.f;
                    }
                    const __half2 e = h2exp2(__floats2half2_rn(u0, u1));
                    rowAcc = __hadd2(rowAcc, e);
                    colAcc[nt] = __hadd2(colAcc[nt], e);
                }
                const float2 rf = __half22float2(rowAcc);
                float s = rf.x + rf.y;
                s += __shfl_xor_sync(0xffffffffu, s, 1);
                s += __shfl_xor_sync(0xffffffffu, s, 2);
                if ((lane & 3) == 0) atomicAdd(&g_rowsum[gr], s);
            }

        if (offdiag) {
#pragma unroll
            for (int nt = 0; nt < 4; nt++) {
                __half2 hc = colAcc[nt];
#pragma unroll
                for (int o = 4; o <= 16; o <<= 1) {
                    uint32_t u = *reinterpret_cast<uint32_t*>(&hc);
                    uint32_t pc = __shfl_xor_sync(0xffffffffu, u, o);
                    hc = __hadd2(hc, *reinterpret_cast<__half2*>(&pc));
                }
                if ((lane >> 2) == 0) {
                    const float2 f = __half22float2(hc);
                    const int gc0 = col0 + warpN0 + nt * 8 + (lane & 3) * 2;
                    atomicAdd(&g_rowsum[gc0], f.x);
                    atomicAdd(&g_rowsum[gc0 + 1], f.y);
                }
            }
        }
        __syncthreads();   // protect smem labels/ticket before next tile
    }
}

// ---------------------------------------------------------------------------
// One warp per row: base = SHIFT + log(rowsum); sum softplus(base - l).
// Last warp (ticket) finalizes the output.
__global__ void pair_kernel(float* out) {
    const int warp = (blockIdx.x * blockDim.x + threadIdx.x) >> 5;
    const int lane = threadIdx.x & 31;
    if (warp >= BDIM) return;
    int cnt = g_plcnt[warp];
    if (cnt > PLCAP) cnt = PLCAP;
    const float base = SHIFT + __logf(g_rowsum[warp]);
    float rowsum = 0.f;
    for (int t = lane; t < cnt; t += 32) {
        const float l = g_pl[warp * PLCAP + t];
        const float x = base - l;
        rowsum += (x > 0.f) ? x + __logf(1.f + __expf(-x)) : __logf(1.f + __expf(x));
    }
#pragma unroll
    for (int o = 16; o > 0; o >>= 1) rowsum += __shfl_xor_sync(0xffffffffu, rowsum, o);

    if (lane == 0) {
        if (cnt > 0) atomicAdd(&g_acc, (double)(rowsum / (float)cnt));
        __threadfence();
        const int t = atomicAdd(&g_ticket, 1);
        if (t == BDIM - 1) {
            __threadfence();
            const double total = atomicAdd(&g_acc, 0.0);
            out[0] = (float)(total / (double)BDIM);
        }
    }
}

// ---------------------------------------------------------------------------
extern "C" void kernel_launch(void* const* d_in, const int* in_sizes, int n_in,
                              void* d_out, int out_size) {
    const float* E   = nullptr;
    const int*   lab = nullptr;
    for (int i = 0; i < n_in; i++) {
        if (in_sizes[i] == BDIM * DDIM) E   = (const float*)d_in[i];
        else if (in_sizes[i] == BDIM)   lab = (const int*)d_in[i];
    }
    float* out = (float*)d_out;

    cudaFuncSetAttribute(lse_gemm_kernel,
                         cudaFuncAttributeMaxDynamicSharedMemorySize, SMEM_BYTES);

    convert_kernel<<<(BDIM * DDIM / 4) / 256, 256>>>(E);
    lse_gemm_kernel<<<GRID_GEMM, 256, SMEM_BYTES>>>(lab);
    pair_kernel<<<BDIM / 8, 256>>>(out);
}